// round 5
// baseline (speedup 1.0000x reference)
#include <cuda_runtime.h>

#define NBATCH 16
#define CC     256
#define NOUT   103
#define DOUT   16
#define NJO    (NOUT*DOUT)     /* 1648 */
#define NH1    5562
#define NH2    12514
#define NREC   8343

// ---------------- scratch (__device__ globals: no allocation allowed) ----------
__device__ float g_p   [NBATCH*CC];
__device__ float g_sq  [NBATCH*CC];
__device__ float g_Wsum[CC*NJO];
__device__ float g_bij [CC*NOUT];
__device__ float g_s   [NBATCH*NJO];
__device__ float g_fac [NBATCH*DOUT];
__device__ float g_f0  [NBATCH*NJO];
__device__ float g_f1  [NBATCH*NH1];
__device__ float g_f2  [NBATCH*NH2];

// ---------------- packed f32x2 helpers -----------------------------------------
__device__ __forceinline__ unsigned long long packdup(float w){
    unsigned long long r;
    asm("mov.b64 %0, {%1, %1};" : "=l"(r) : "r"(__float_as_uint(w)));
    return r;
}
__device__ __forceinline__ unsigned long long pack2(float lo, float hi){
    unsigned long long r;
    asm("mov.b64 %0, {%1, %2};" : "=l"(r) : "r"(__float_as_uint(lo)), "r"(__float_as_uint(hi)));
    return r;
}
__device__ __forceinline__ void ffma2(unsigned long long &d, unsigned long long a, unsigned long long b){
    asm("fma.rn.f32x2 %0, %1, %2, %3;" : "=l"(d) : "l"(a), "l"(b), "l"(d));
}

// ---------------- conv 3x3 VALID + bias + relu + spatial mean ------------------
// grid = 256 (one block per out channel), block = 256
__global__ void conv_mean_k(const float* __restrict__ x, const float* __restrict__ w,
                            const float* __restrict__ bias){
    int oc = blockIdx.x;
    int tid = threadIdx.x;
    __shared__ float ws[927];
    __shared__ float accs[NBATCH];
    for (int i = tid; i < 927; i += 256) ws[i] = w[oc*927 + i];
    if (tid < NBATCH) accs[tid] = 0.f;
    __syncthreads();
    float bb = bias[oc];
    for (int item = tid; item < NBATCH*49; item += 256){
        int b = item / 49, pos = item % 49;
        int y = pos / 7, xx = pos % 7;
        const float* xb = x + b*103*81 + y*9 + xx;
        float acc = bb;
        #pragma unroll 1
        for (int ic = 0; ic < 103; ic++){
            const float* xp = xb + ic*81;
            const float* wp = ws + ic*9;
            acc += xp[0]*wp[0] + xp[1]*wp[1] + xp[2]*wp[2];
            acc += xp[9]*wp[3] + xp[10]*wp[4] + xp[11]*wp[5];
            acc += xp[18]*wp[6] + xp[19]*wp[7] + xp[20]*wp[8];
        }
        acc = fmaxf(acc, 0.f);
        atomicAdd(&accs[b], acc);
    }
    __syncthreads();
    if (tid < NBATCH) g_p[tid*CC + oc] = accs[tid] * (1.f/49.f);
}

// ---------------- squash p over channels ---------------------------------------
// grid = 16, block = 256
__global__ void squash_p_k(){
    int b = blockIdx.x, t = threadIdx.x;
    __shared__ float red[256];
    float v = g_p[b*CC + t];
    red[t] = v*v; __syncthreads();
    for (int s = 128; s > 0; s >>= 1){ if (t < s) red[t] += red[t+s]; __syncthreads(); }
    float msq = red[0];
    float fac = msq / ((1.f + msq) * sqrtf(msq));
    g_sq[b*CC + t] = v * fac;
}

// ---------------- Wsum[c,j,o] = sum_i W_caps[c,j,o,i] --------------------------
// grid = 1648, block = 256
__global__ void wsum_k(const float* __restrict__ Wc){
    int idx = blockIdx.x*256 + threadIdx.x;
    if (idx >= CC*NJO) return;
    const float4* s = (const float4*)(Wc + (size_t)idx*32);
    float acc = 0.f;
    #pragma unroll
    for (int i = 0; i < 8; i++){ float4 v = s[i]; acc += v.x + v.y + v.z + v.w; }
    g_Wsum[idx] = acc;
}

// ---------------- b_ij init ----------------------------------------------------
__global__ void binit_k(){
    int i = blockIdx.x*256 + threadIdx.x;
    if (i < CC*NOUT) g_bij[i] = 1.f;
}

// ---------------- routing: softmax over c + s_j --------------------------------
// grid = 103 (j), block = 256
__global__ void route_s_k(){
    int j = blockIdx.x, t = threadIdx.x;
    __shared__ float red[256];
    __shared__ float cij[256];
    __shared__ float sqs[NBATCH*CC];
    float bv = g_bij[t*NOUT + j];
    red[t] = bv; __syncthreads();
    for (int s = 128; s > 0; s >>= 1){ if (t < s) red[t] = fmaxf(red[t], red[t+s]); __syncthreads(); }
    float mx = red[0]; __syncthreads();
    float e = expf(bv - mx);
    red[t] = e; __syncthreads();
    for (int s = 128; s > 0; s >>= 1){ if (t < s) red[t] += red[t+s]; __syncthreads(); }
    cij[t] = e / red[0];
    for (int i = t; i < NBATCH*CC; i += 256) sqs[i] = g_sq[i];
    __syncthreads();
    int b = t >> 4, o = t & 15;
    const float* Wj = g_Wsum + j*DOUT + o;
    const float* sqb = sqs + b*CC;
    float acc = 0.f;
    #pragma unroll 4
    for (int c = 0; c < CC; c++) acc += cij[c]*sqb[c]*Wj[c*NJO];
    g_s[(b*NOUT + j)*DOUT + o] = acc;
}

// ---------------- routing: squash factor over j (axis=2) -----------------------
// grid = 1, block = 256  (thread = (b,o); reduce over j)
__global__ void route_fac_k(){
    int t = threadIdx.x;
    int b = t >> 4, o = t & 15;
    const float* sp = g_s + b*NJO + o;
    float acc = 0.f;
    for (int j = 0; j < NOUT; j++){ float v = sp[j*DOUT]; acc += v*v; }
    g_fac[t] = acc / ((1.f + acc) * sqrtf(acc));
}

// ---------------- routing: agreement + b update --------------------------------
// grid = 103 (j), block = 256 (thread = c)
__global__ void route_upd_k(){
    int j = blockIdx.x, t = threadIdx.x;
    __shared__ float vs[256];
    int b = t >> 4, o = t & 15;
    vs[t] = g_s[(b*NOUT + j)*DOUT + o] * g_fac[t];
    __syncthreads();
    float wreg[16];
    const float* Wc = g_Wsum + t*NJO + j*DOUT;
    #pragma unroll
    for (int q = 0; q < 16; q++) wreg[q] = Wc[q];
    float acc = 0.f;
    #pragma unroll 2
    for (int b2 = 0; b2 < NBATCH; b2++){
        float d = 0.f;
        #pragma unroll
        for (int q = 0; q < 16; q++) d += wreg[q]*vs[b2*16 + q];
        acc += g_sq[b2*CC + t] * d;
    }
    g_bij[t*NOUT + j] += acc * (1.f/NBATCH);
}

// ---------------- final: v, ba, f0 = v*||v|| -----------------------------------
// grid = 103, block = 256
__global__ void route_f0_k(float* __restrict__ out_ba){
    int j = blockIdx.x, t = threadIdx.x;
    __shared__ float vsq[256];
    __shared__ float bas[NBATCH];
    int b = t >> 4, o = t & 15;
    float v = g_s[(b*NOUT + j)*DOUT + o] * g_fac[t];
    vsq[t] = v*v;
    __syncthreads();
    if (o == 0){
        float s = 0.f;
        #pragma unroll
        for (int q = 0; q < 16; q++) s += vsq[b*16 + q];
        float ba = sqrtf(s);
        bas[b] = ba;
        out_ba[b*NOUT + j] = ba;
    }
    __syncthreads();
    g_f0[b*NJO + j*DOUT + o] = v * bas[b];
}

// ---------------- out[b,n] = bias[n] -------------------------------------------
__global__ void bias_init_k(float* __restrict__ out, const float* __restrict__ bias, int N){
    int i = blockIdx.x*256 + threadIdx.x;
    if (i < NBATCH*N) out[i] = bias[i % N];
}

// ---------------- skinny GEMM: out(16,N) += A(16,K) @ W(K,N) -------------------
// block = 128 threads, tile = 512 columns (4 cols/thread strided by 128),
// 16 batch rows packed as 8 f32x2 accumulators, split-K over grid.y, atomicAdd out.
template<bool GUARD>
__device__ __forceinline__ void gemm_body(const float* __restrict__ A, const float* __restrict__ W,
                                          float* __restrict__ out, int K, int N, int kPerSplit){
    __shared__ unsigned long long sA[256*8];
    int tid = threadIdx.x;
    int n0  = blockIdx.x*512;
    int ks  = blockIdx.y*kPerSplit;
    int ke  = min(ks + kPerSplit, K);
    int nb  = n0 + tid;
    bool ok0 = (!GUARD) || (nb       < N);
    bool ok1 = (!GUARD) || (nb + 128 < N);
    bool ok2 = (!GUARD) || (nb + 256 < N);
    bool ok3 = (!GUARD) || (nb + 384 < N);

    unsigned long long acc[4][8];
    #pragma unroll
    for (int c = 0; c < 4; c++)
        #pragma unroll
        for (int p = 0; p < 8; p++) acc[c][p] = 0ull;

    for (int k0 = ks; k0 < ke; k0 += 256){
        int kc = min(256, ke - k0);
        __syncthreads();
        for (int i = tid; i < kc*8; i += 128){
            int kk = i >> 3, p = i & 7;
            float lo = A[(2*p  )*K + k0 + kk];
            float hi = A[(2*p+1)*K + k0 + kk];
            sA[i] = pack2(lo, hi);
        }
        __syncthreads();
        const float* wp = W + (long long)k0*N + nb;
        #pragma unroll 2
        for (int kk = 0; kk < kc; kk++){
            unsigned long long f[8];
            #pragma unroll
            for (int p = 0; p < 8; p++) f[p] = sA[kk*8 + p];
            float w0, w1, w2, w3;
            if (GUARD){
                w0 = ok0 ? wp[0]   : 0.f;
                w1 = ok1 ? wp[128] : 0.f;
                w2 = ok2 ? wp[256] : 0.f;
                w3 = ok3 ? wp[384] : 0.f;
            } else {
                w0 = wp[0]; w1 = wp[128]; w2 = wp[256]; w3 = wp[384];
            }
            unsigned long long ww0 = packdup(w0);
            unsigned long long ww1 = packdup(w1);
            unsigned long long ww2 = packdup(w2);
            unsigned long long ww3 = packdup(w3);
            #pragma unroll
            for (int p = 0; p < 8; p++) ffma2(acc[0][p], f[p], ww0);
            #pragma unroll
            for (int p = 0; p < 8; p++) ffma2(acc[1][p], f[p], ww1);
            #pragma unroll
            for (int p = 0; p < 8; p++) ffma2(acc[2][p], f[p], ww2);
            #pragma unroll
            for (int p = 0; p < 8; p++) ffma2(acc[3][p], f[p], ww3);
            wp += N;
        }
    }
    #pragma unroll
    for (int c = 0; c < 4; c++){
        int n = nb + c*128;
        if (GUARD && n >= N) continue;
        #pragma unroll
        for (int p = 0; p < 8; p++){
            unsigned long long a = acc[c][p];
            float lo = __uint_as_float((unsigned)(a & 0xffffffffu));
            float hi = __uint_as_float((unsigned)(a >> 32));
            atomicAdd(out + (2*p  )*N + n, lo);
            atomicAdd(out + (2*p+1)*N + n, hi);
        }
    }
}

__global__ void __launch_bounds__(128) gemm16_k(const float* __restrict__ A, const float* __restrict__ W,
                                                float* __restrict__ out, int K, int N, int kPerSplit){
    if (blockIdx.x*512 + 512 <= N) gemm_body<false>(A, W, out, K, N, kPerSplit);
    else                           gemm_body<true >(A, W, out, K, N, kPerSplit);
}

// ---------------- launch -------------------------------------------------------
extern "C" void kernel_launch(void* const* d_in, const int* in_sizes, int n_in,
                              void* d_out, int out_size){
    const float* x      = (const float*)d_in[0];
    const float* conv_w = (const float*)d_in[1];
    const float* conv_b = (const float*)d_in[2];
    const float* W_caps = (const float*)d_in[3];
    const float* fc1_w  = (const float*)d_in[4];
    const float* fc1_b  = (const float*)d_in[5];
    const float* fc2_w  = (const float*)d_in[6];
    const float* fc2_b  = (const float*)d_in[7];
    const float* fc3_w  = (const float*)d_in[8];
    const float* fc3_b  = (const float*)d_in[9];
    float* out = (float*)d_out;               // [0,1648): ba, [1648, 135136): recon
    float* out_recon = out + NBATCH*NOUT;

    float *p_f0, *p_f1, *p_f2;
    cudaGetSymbolAddress((void**)&p_f0, g_f0);
    cudaGetSymbolAddress((void**)&p_f1, g_f1);
    cudaGetSymbolAddress((void**)&p_f2, g_f2);

    conv_mean_k<<<256, 256>>>(x, conv_w, conv_b);
    squash_p_k <<<16, 256>>>();
    wsum_k     <<<(CC*NJO + 255)/256, 256>>>(W_caps);
    binit_k    <<<(CC*NOUT + 255)/256, 256>>>();

    for (int it = 0; it < 3; it++){
        route_s_k  <<<NOUT, 256>>>();
        route_fac_k<<<1, 256>>>();
        if (it < 2) route_upd_k<<<NOUT, 256>>>();
        else        route_f0_k <<<NOUT, 256>>>(out);
    }

    // fc1: (16,1648) @ (1648,5562)
    bias_init_k<<<(NBATCH*NH1 + 255)/256, 256>>>(p_f1, fc1_b, NH1);
    gemm16_k<<<dim3((NH1 + 511)/512, 16), 128>>>(p_f0, fc1_w, p_f1, NJO, NH1, 103);
    // fc2: (16,5562) @ (5562,12514)
    bias_init_k<<<(NBATCH*NH2 + 255)/256, 256>>>(p_f2, fc2_b, NH2);
    gemm16_k<<<dim3((NH2 + 511)/512, 12), 128>>>(p_f1, fc2_w, p_f2, NH1, NH2, 464);
    // fc3: (16,12514) @ (12514,8343) -> recon
    bias_init_k<<<(NBATCH*NREC + 255)/256, 256>>>(out_recon, fc3_b, NREC);
    gemm16_k<<<dim3((NREC + 511)/512, 16), 128>>>(p_f2, fc3_w, out_recon, NH2, NREC, 783);
}

// round 16
// speedup vs baseline: 1.8439x; 1.8439x over previous
#include <cuda_runtime.h>

#define NBATCH 16
#define CC     256
#define NOUT   103
#define DOUT   16
#define NJO    (NOUT*DOUT)     /* 1648 */
#define NH1    5562
#define NH2    12514
#define NREC   8343

// ---------------- scratch (__device__ globals: no allocation allowed) ----------
__device__ float g_p   [NBATCH*CC];
__device__ float g_sq  [NBATCH*CC];
__device__ float g_Wsum[CC*NJO];
__device__ float g_bij [CC*NOUT];
__device__ float g_s   [NBATCH*NJO];
__device__ float g_ssq [3][NBATCH*DOUT];   // per-iter sum_j s^2, built by atomics
__device__ float g_f0  [NBATCH*NJO];
__device__ float g_f1  [NBATCH*NH1];
__device__ float g_f2  [NBATCH*NH2];

// ---------------- packed f32x2 helpers -----------------------------------------
__device__ __forceinline__ unsigned long long packdup(float w){
    unsigned long long r;
    asm("mov.b64 %0, {%1, %1};" : "=l"(r) : "r"(__float_as_uint(w)));
    return r;
}
__device__ __forceinline__ unsigned long long pack2(float lo, float hi){
    unsigned long long r;
    asm("mov.b64 %0, {%1, %2};" : "=l"(r) : "r"(__float_as_uint(lo)), "r"(__float_as_uint(hi)));
    return r;
}
__device__ __forceinline__ void ffma2(unsigned long long &d, unsigned long long a, unsigned long long b){
    asm("fma.rn.f32x2 %0, %1, %2, %3;" : "=l"(d) : "l"(a), "l"(b), "l"(d));
}

// ---------------- bias pre-init for all three GEMM outputs (no deps, runs first)
__global__ void bias_all_k(const float* __restrict__ b1, const float* __restrict__ b2,
                           const float* __restrict__ b3, float* __restrict__ recon){
    int i = blockIdx.x*256 + threadIdx.x;
    if (i < NBATCH*NH1){ g_f1[i] = b1[i % NH1]; return; }
    i -= NBATCH*NH1;
    if (i < NBATCH*NH2){ g_f2[i] = b2[i % NH2]; return; }
    i -= NBATCH*NH2;
    if (i < NBATCH*NREC){ recon[i] = b3[i % NREC]; }
}

// ---------------- conv 3x3 VALID + bias + relu + spatial mean ------------------
// grid = 256 (one block per out channel), block = 256
__global__ void conv_mean_k(const float* __restrict__ x, const float* __restrict__ w,
                            const float* __restrict__ bias){
    int oc = blockIdx.x;
    int tid = threadIdx.x;
    __shared__ float ws[927];
    __shared__ float accs[NBATCH];
    for (int i = tid; i < 927; i += 256) ws[i] = w[oc*927 + i];
    if (tid < NBATCH) accs[tid] = 0.f;
    __syncthreads();
    float bb = bias[oc];
    for (int item = tid; item < NBATCH*49; item += 256){
        int b = item / 49, pos = item % 49;
        int y = pos / 7, xx = pos % 7;
        const float* xb = x + b*103*81 + y*9 + xx;
        float acc = bb;
        #pragma unroll 2
        for (int ic = 0; ic < 103; ic++){
            const float* xp = xb + ic*81;
            const float* wp = ws + ic*9;
            acc += xp[0]*wp[0] + xp[1]*wp[1] + xp[2]*wp[2];
            acc += xp[9]*wp[3] + xp[10]*wp[4] + xp[11]*wp[5];
            acc += xp[18]*wp[6] + xp[19]*wp[7] + xp[20]*wp[8];
        }
        acc = fmaxf(acc, 0.f);
        atomicAdd(&accs[b], acc);
    }
    __syncthreads();
    if (tid < NBATCH) g_p[tid*CC + oc] = accs[tid] * (1.f/49.f);
}

// ---------------- squash p over channels (+ zero the ssq slots) -----------------
// grid = 16, block = 256
__global__ void squash_p_k(){
    int b = blockIdx.x, t = threadIdx.x;
    __shared__ float red[256];
    if (b == 0){
        float* z = (float*)g_ssq;
        for (int i = t; i < 3*NBATCH*DOUT; i += 256) z[i] = 0.f;
    }
    float v = g_p[b*CC + t];
    red[t] = v*v; __syncthreads();
    for (int s = 128; s > 0; s >>= 1){ if (t < s) red[t] += red[t+s]; __syncthreads(); }
    float msq = red[0];
    float fac = msq / ((1.f + msq) * sqrtf(msq));
    g_sq[b*CC + t] = v * fac;
}

// ---------------- Wsum[c,j,o] = sum_i W_caps[c,j,o,i] --------------------------
// grid = 1648, block = 256
__global__ void wsum_k(const float* __restrict__ Wc){
    int idx = blockIdx.x*256 + threadIdx.x;
    if (idx >= CC*NJO) return;
    const float4* s = (const float4*)(Wc + (size_t)idx*32);
    float acc = 0.f;
    #pragma unroll
    for (int i = 0; i < 8; i++){ float4 v = s[i]; acc += v.x + v.y + v.z + v.w; }
    g_Wsum[idx] = acc;
}

// ---------------- routing: softmax over c + s_j (+ atomic ssq) ------------------
// grid = 103 (j), block = 256. iter==0: uniform c_ij = 1/256 exactly.
__global__ void route_s_k(int iter){
    int j = blockIdx.x, t = threadIdx.x;
    __shared__ float red[256];
    __shared__ float cij[256];
    __shared__ float sqs[NBATCH*CC];
    __shared__ float sW [CC*DOUT];
    for (int i = t; i < NBATCH*CC; i += 256) sqs[i] = g_sq[i];
    // coalesced float4 stage of Wsum[:, j*16 .. j*16+16)
    #pragma unroll
    for (int r = 0; r < 4; r++){
        int f4 = r*256 + t;
        int c = f4 >> 2, qv = (f4 & 3) << 2;
        float4 v = *(const float4*)(g_Wsum + c*NJO + j*DOUT + qv);
        *(float4*)(sW + c*DOUT + qv) = v;
    }
    if (iter > 0){
        float bv = g_bij[t*NOUT + j];
        red[t] = bv; __syncthreads();
        for (int s = 128; s > 0; s >>= 1){ if (t < s) red[t] = fmaxf(red[t], red[t+s]); __syncthreads(); }
        float mx = red[0]; __syncthreads();
        float e = expf(bv - mx);
        red[t] = e; __syncthreads();
        for (int s = 128; s > 0; s >>= 1){ if (t < s) red[t] += red[t+s]; __syncthreads(); }
        cij[t] = e / red[0];
    } else {
        cij[t] = 1.f/256.f;
    }
    __syncthreads();
    int b = t >> 4, o = t & 15;
    const float* sqb = sqs + b*CC;
    float acc = 0.f;
    #pragma unroll 8
    for (int c = 0; c < CC; c++) acc += cij[c]*sqb[c]*sW[c*DOUT + o];
    g_s[(b*NOUT + j)*DOUT + o] = acc;
    atomicAdd(&g_ssq[iter][t], acc*acc);
}

// ---------------- routing: agreement + b update (fac from ssq) ------------------
// grid = 103 (j), block = 256 (thread = c in second phase)
__global__ void route_upd_k(int iter){
    int j = blockIdx.x, t = threadIdx.x;
    __shared__ float vs[256];
    int b = t >> 4, o = t & 15;
    float msq = g_ssq[iter][t];
    float fac = msq / ((1.f + msq) * sqrtf(msq));
    vs[t] = g_s[(b*NOUT + j)*DOUT + o] * fac;
    __syncthreads();
    const float* Wc = g_Wsum + t*NJO + j*DOUT;
    float4 w0 = *(const float4*)(Wc);
    float4 w1 = *(const float4*)(Wc + 4);
    float4 w2 = *(const float4*)(Wc + 8);
    float4 w3 = *(const float4*)(Wc + 12);
    float wreg[16] = {w0.x,w0.y,w0.z,w0.w, w1.x,w1.y,w1.z,w1.w,
                      w2.x,w2.y,w2.z,w2.w, w3.x,w3.y,w3.z,w3.w};
    float acc = 0.f;
    #pragma unroll 2
    for (int b2 = 0; b2 < NBATCH; b2++){
        float d = 0.f;
        #pragma unroll
        for (int q = 0; q < 16; q++) d += wreg[q]*vs[b2*16 + q];
        acc += g_sq[b2*CC + t] * d;
    }
    if (iter == 0) g_bij[t*NOUT + j] = 1.f + acc * (1.f/NBATCH);
    else           g_bij[t*NOUT + j] += acc * (1.f/NBATCH);
}

// ---------------- final: v, ba, f0 = v*||v|| -----------------------------------
// grid = 103, block = 256
__global__ void route_f0_k(float* __restrict__ out_ba){
    int j = blockIdx.x, t = threadIdx.x;
    __shared__ float vsq[256];
    __shared__ float bas[NBATCH];
    int b = t >> 4, o = t & 15;
    float msq = g_ssq[2][t];
    float fac = msq / ((1.f + msq) * sqrtf(msq));
    float v = g_s[(b*NOUT + j)*DOUT + o] * fac;
    vsq[t] = v*v;
    __syncthreads();
    if (o == 0){
        float s = 0.f;
        #pragma unroll
        for (int q = 0; q < 16; q++) s += vsq[b*16 + q];
        float ba = sqrtf(s);
        bas[b] = ba;
        out_ba[b*NOUT + j] = ba;
    }
    __syncthreads();
    g_f0[b*NJO + j*DOUT + o] = v * bas[b];
}

// ---------------- skinny GEMM: out(16,N) += A(16,K) @ W(K,N) -------------------
// block = 128 threads, tile = 512 columns (4 cols/thread strided by 128),
// 16 batch rows as 8 f32x2 accumulators; 8-kk groups with 32 batched streaming
// W loads per thread for MLP; split-K over grid.y, atomicAdd epilogue.
template<bool GUARD>
__device__ __forceinline__ void gemm_body(const float* __restrict__ A, const float* __restrict__ W,
                                          float* __restrict__ out, int K, int N, int kPerSplit){
    __shared__ unsigned long long sA[256*8];
    int tid = threadIdx.x;
    int n0  = blockIdx.x*512;
    int ks  = blockIdx.y*kPerSplit;
    int ke  = min(ks + kPerSplit, K);
    int nb  = n0 + tid;
    bool ok0 = (!GUARD) || (nb       < N);
    bool ok1 = (!GUARD) || (nb + 128 < N);
    bool ok2 = (!GUARD) || (nb + 256 < N);
    bool ok3 = (!GUARD) || (nb + 384 < N);

    unsigned long long acc[4][8];
    #pragma unroll
    for (int c = 0; c < 4; c++)
        #pragma unroll
        for (int p = 0; p < 8; p++) acc[c][p] = 0ull;

    for (int k0 = ks; k0 < ke; k0 += 256){
        int kc = min(256, ke - k0);
        __syncthreads();
        for (int i = tid; i < kc*8; i += 128){
            int kk = i >> 3, p = i & 7;
            float lo = A[(2*p  )*K + k0 + kk];
            float hi = A[(2*p+1)*K + k0 + kk];
            sA[i] = pack2(lo, hi);
        }
        __syncthreads();
        const float* wbase = W + (long long)k0*N + nb;
        int kk = 0;
        for (; kk + 8 <= kc; kk += 8){
            float w[8][4];
            #pragma unroll
            for (int u = 0; u < 8; u++){
                const float* wp = wbase + (long long)(kk + u)*N;
                if (GUARD){
                    w[u][0] = ok0 ? __ldcs(wp)       : 0.f;
                    w[u][1] = ok1 ? __ldcs(wp + 128) : 0.f;
                    w[u][2] = ok2 ? __ldcs(wp + 256) : 0.f;
                    w[u][3] = ok3 ? __ldcs(wp + 384) : 0.f;
                } else {
                    w[u][0] = __ldcs(wp);
                    w[u][1] = __ldcs(wp + 128);
                    w[u][2] = __ldcs(wp + 256);
                    w[u][3] = __ldcs(wp + 384);
                }
            }
            #pragma unroll
            for (int u = 0; u < 8; u++){
                unsigned long long f[8];
                #pragma unroll
                for (int p = 0; p < 8; p++) f[p] = sA[(kk + u)*8 + p];
                unsigned long long ww;
                ww = packdup(w[u][0]);
                #pragma unroll
                for (int p = 0; p < 8; p++) ffma2(acc[0][p], f[p], ww);
                ww = packdup(w[u][1]);
                #pragma unroll
                for (int p = 0; p < 8; p++) ffma2(acc[1][p], f[p], ww);
                ww = packdup(w[u][2]);
                #pragma unroll
                for (int p = 0; p < 8; p++) ffma2(acc[2][p], f[p], ww);
                ww = packdup(w[u][3]);
                #pragma unroll
                for (int p = 0; p < 8; p++) ffma2(acc[3][p], f[p], ww);
            }
        }
        for (; kk < kc; kk++){
            const float* wp = wbase + (long long)kk*N;
            float w0 = (!GUARD || ok0) ? __ldcs(wp)       : 0.f;
            float w1 = (!GUARD || ok1) ? __ldcs(wp + 128) : 0.f;
            float w2 = (!GUARD || ok2) ? __ldcs(wp + 256) : 0.f;
            float w3 = (!GUARD || ok3) ? __ldcs(wp + 384) : 0.f;
            unsigned long long f[8];
            #pragma unroll
            for (int p = 0; p < 8; p++) f[p] = sA[kk*8 + p];
            unsigned long long ww;
            ww = packdup(w0);
            #pragma unroll
            for (int p = 0; p < 8; p++) ffma2(acc[0][p], f[p], ww);
            ww = packdup(w1);
            #pragma unroll
            for (int p = 0; p < 8; p++) ffma2(acc[1][p], f[p], ww);
            ww = packdup(w2);
            #pragma unroll
            for (int p = 0; p < 8; p++) ffma2(acc[2][p], f[p], ww);
            ww = packdup(w3);
            #pragma unroll
            for (int p = 0; p < 8; p++) ffma2(acc[3][p], f[p], ww);
        }
    }
    #pragma unroll
    for (int c = 0; c < 4; c++){
        int n = nb + c*128;
        if (GUARD && n >= N) continue;
        #pragma unroll
        for (int p = 0; p < 8; p++){
            unsigned long long a = acc[c][p];
            float lo = __uint_as_float((unsigned)(a & 0xffffffffu));
            float hi = __uint_as_float((unsigned)(a >> 32));
            atomicAdd(out + (2*p  )*N + n, lo);
            atomicAdd(out + (2*p+1)*N + n, hi);
        }
    }
}

__global__ void __launch_bounds__(128) gemm16_k(const float* __restrict__ A, const float* __restrict__ W,
                                                float* __restrict__ out, int K, int N, int kPerSplit){
    if (blockIdx.x*512 + 512 <= N) gemm_body<false>(A, W, out, K, N, kPerSplit);
    else                           gemm_body<true >(A, W, out, K, N, kPerSplit);
}

// ---------------- launch -------------------------------------------------------
extern "C" void kernel_launch(void* const* d_in, const int* in_sizes, int n_in,
                              void* d_out, int out_size){
    const float* x      = (const float*)d_in[0];
    const float* conv_w = (const float*)d_in[1];
    const float* conv_b = (const float*)d_in[2];
    const float* W_caps = (const float*)d_in[3];
    const float* fc1_w  = (const float*)d_in[4];
    const float* fc1_b  = (const float*)d_in[5];
    const float* fc2_w  = (const float*)d_in[6];
    const float* fc2_b  = (const float*)d_in[7];
    const float* fc3_w  = (const float*)d_in[8];
    const float* fc3_b  = (const float*)d_in[9];
    float* out = (float*)d_out;               // [0,1648): ba, [1648, 135136): recon
    float* out_recon = out + NBATCH*NOUT;

    float *p_f0, *p_f1, *p_f2;
    cudaGetSymbolAddress((void**)&p_f0, g_f0);
    cudaGetSymbolAddress((void**)&p_f1, g_f1);
    cudaGetSymbolAddress((void**)&p_f2, g_f2);

    int biasTotal = NBATCH*(NH1 + NH2 + NREC);
    bias_all_k <<<(biasTotal + 255)/256, 256>>>(fc1_b, fc2_b, fc3_b, out_recon);
    conv_mean_k<<<256, 256>>>(x, conv_w, conv_b);
    squash_p_k <<<16, 256>>>();
    wsum_k     <<<(CC*NJO + 255)/256, 256>>>(W_caps);

    for (int it = 0; it < 3; it++){
        route_s_k<<<NOUT, 256>>>(it);
        if (it < 2) route_upd_k<<<NOUT, 256>>>(it);
        else        route_f0_k <<<NOUT, 256>>>(out);
    }

    // fc1: (16,1648) @ (1648,5562)   23 splits x 72 (multiples of 8)
    gemm16_k<<<dim3((NH1 + 511)/512, 23), 128>>>(p_f0, fc1_w, p_f1, NJO, NH1, 72);
    // fc2: (16,5562) @ (5562,12514)  12 splits x 464
    gemm16_k<<<dim3((NH2 + 511)/512, 12), 128>>>(p_f1, fc2_w, p_f2, NH1, NH2, 464);
    // fc3: (16,12514) @ (12514,8343) 16 splits x 784
    gemm16_k<<<dim3((NREC + 511)/512, 16), 128>>>(p_f2, fc3_w, out_recon, NH2, NREC, 784);
}